// round 7
// baseline (speedup 1.0000x reference)
#include <cuda_runtime.h>
#include <cstdint>

// FastAttention (Performer / FAVOR+) — B=4 H=8 N=4096 D=64 M=266 E=64.
// Round 7: k_ctx_mma rewritten — hi/lo tf32 pre-split at staging (pure
// LDS.64+HMMA inner loop), chunk 32, occupancy 3 CTAs/SM. k_out bounds (256,3).

#define BHc 32
#define NN  4096
#define DD  64
#define MM  266
#define MSTR 272
#define EE  64
#define ECT 80            // ctx cols: 64 v + ones(kcum) at 64 + 15 zero pad

#define DN     0.3535533905932738f
#define RATIO  0.06131393394849658f
#define EPSV   1e-4f
#define NEGINF (-3.402823466e38f)

#define SPLITC 2

// ---- scratch ----
__device__ float    g_qp[BHc * NN * MSTR];       // q' (pads [266,272) stay 0)
__device__ float    g_kd[BHc * NN * MSTR];       // dash - diag (pads stay 0)
__device__ unsigned g_kmax_bits;
__device__ float    g_ctx_part[SPLITC * BHc * ECT * MSTR];
__device__ float    g_ctxT[BHc * ECT * MSTR];    // [bh][e][m]; row 64 = kcum

__global__ void k_reset() { if (threadIdx.x == 0) g_kmax_bits = 0u; }

// =====================  mma.sync helpers  ======================

__device__ __forceinline__ uint32_t f2tf32(float x) {
    uint32_t r; asm("cvt.rna.tf32.f32 %0, %1;" : "=r"(r) : "f"(x)); return r;
}
__device__ __forceinline__ void mma8(float* d, const uint32_t* a, const uint32_t* b) {
    asm volatile(
        "mma.sync.aligned.m16n8k8.row.col.f32.tf32.tf32.f32 "
        "{%0,%1,%2,%3}, {%4,%5,%6,%7}, {%8,%9}, {%0,%1,%2,%3};"
        : "+f"(d[0]), "+f"(d[1]), "+f"(d[2]), "+f"(d[3])
        : "r"(a[0]), "r"(a[1]), "r"(a[2]), "r"(a[3]), "r"(b[0]), "r"(b[1]));
}
__device__ __forceinline__ void splitA(const float* ax, int strd, uint32_t* aH, uint32_t* aL) {
    float a0 = ax[0], a1 = ax[8 * strd], a2 = ax[4], a3 = ax[8 * strd + 4];
    aH[0] = f2tf32(a0); aL[0] = f2tf32(a0 - __uint_as_float(aH[0]));
    aH[1] = f2tf32(a1); aL[1] = f2tf32(a1 - __uint_as_float(aH[1]));
    aH[2] = f2tf32(a2); aL[2] = f2tf32(a2 - __uint_as_float(aH[2]));
    aH[3] = f2tf32(a3); aL[3] = f2tf32(a3 - __uint_as_float(aH[3]));
}
__device__ __forceinline__ void splitB(const float* bx, uint32_t* bH, uint32_t* bL) {
    float b0 = bx[0], b1 = bx[4];
    bH[0] = f2tf32(b0); bL[0] = f2tf32(b0 - __uint_as_float(bH[0]));
    bH[1] = f2tf32(b1); bL[1] = f2tf32(b1 - __uint_as_float(bH[1]));
}
__device__ __forceinline__ uint2 hilo(float x) {
    uint32_t h = f2tf32(x);
    uint32_t l = f2tf32(x - __uint_as_float(h));
    return make_uint2(h, l);
}

// ===========================================================================
// dash GEMM: CTA = 64 n-rows x 272 m x K=64. 8 warps = 4 rowgroups x 2 halves.
// (unchanged from round 6)
// ===========================================================================
#define SXS 68
#define SPS 68

template <bool IS_Q>
__global__ void __launch_bounds__(256, 2) k_dash_mma(const float* __restrict__ X,
                                                     const float* __restrict__ P)
{
    extern __shared__ float sh[];
    float* sX    = sh;                    // [64][68]
    float* sP    = sh + 64 * SXS;         // [272][68]
    float* sDiag = sP + 272 * SPS;        // [64]
    float* sMaxH = sDiag + 64;            // [2][64]
    float* sRed  = sMaxH + 128;           // [8]

    const int tid = threadIdx.x, lane = tid & 31, wid = tid >> 5;
    const int bh = blockIdx.y, n0 = blockIdx.x * 64;

    {   // X tile (scaled) + per-row diag
        const int row = tid >> 2, kq = (tid & 3) * 16;
        const float* src = X + ((size_t)bh * NN + n0 + row) * DD + kq;
        float ss = 0.f;
        #pragma unroll
        for (int j = 0; j < 4; j++) {
            float4 v = *(const float4*)(src + j * 4);
            float x0 = v.x * DN, x1 = v.y * DN, x2 = v.z * DN, x3 = v.w * DN;
            float* d = sX + row * SXS + kq + j * 4;
            d[0] = x0; d[1] = x1; d[2] = x2; d[3] = x3;
            ss = fmaf(x0, x0, ss); ss = fmaf(x1, x1, ss);
            ss = fmaf(x2, x2, ss); ss = fmaf(x3, x3, ss);
        }
        ss += __shfl_xor_sync(0xffffffffu, ss, 1);
        ss += __shfl_xor_sync(0xffffffffu, ss, 2);
        if ((tid & 3) == 0) sDiag[row] = 0.5f * ss;
    }
    for (int t = tid; t < 272 * 4; t += 256) {   // P (zero-padded past 266)
        const int row = t >> 2, kq = (t & 3) * 16;
        const bool valid = row < MM;
        const float* src = P + (size_t)row * DD + kq;
        float* d = sP + row * SPS + kq;
        #pragma unroll
        for (int j = 0; j < 4; j++) {
            float4 v = valid ? *(const float4*)(src + j * 4)
                             : make_float4(0.f, 0.f, 0.f, 0.f);
            d[j * 4 + 0] = v.x; d[j * 4 + 1] = v.y;
            d[j * 4 + 2] = v.z; d[j * 4 + 3] = v.w;
        }
    }
    __syncthreads();

    const int rowGroup = wid >> 1, half = wid & 1;
    const int rA = rowGroup * 16 + (lane >> 2);
    const int colBase = half * 136;

    float acc[17][4];
    #pragma unroll
    for (int t = 0; t < 17; t++)
        #pragma unroll
        for (int j = 0; j < 4; j++) acc[t][j] = 0.f;

    #pragma unroll 1
    for (int k0 = 0; k0 < 64; k0 += 8) {
        uint32_t aH[4], aL[4];
        splitA(sX + (size_t)rA * SXS + k0 + (lane & 3), SXS, aH, aL);
        #pragma unroll
        for (int t = 0; t < 17; t++) {
            uint32_t bH[2], bL[2];
            splitB(sP + (size_t)(colBase + t * 8 + (lane >> 2)) * SPS + k0 + (lane & 3), bH, bL);
            mma8(acc[t], aH, bH);
            mma8(acc[t], aH, bL);
            mma8(acc[t], aL, bH);
        }
    }

    const float dgA = sDiag[rA], dgB = sDiag[rA + 8];

    if (IS_Q) {
        float mA = NEGINF, mB = NEGINF;
        #pragma unroll
        for (int t = 0; t < 17; t++) {
            int m0 = colBase + t * 8 + (lane & 3) * 2;
            if (m0 < MM) {
                mA = fmaxf(mA, fmaxf(acc[t][0], acc[t][1]));
                mB = fmaxf(mB, fmaxf(acc[t][2], acc[t][3]));
            }
        }
        mA = fmaxf(mA, __shfl_xor_sync(0xffffffffu, mA, 1));
        mA = fmaxf(mA, __shfl_xor_sync(0xffffffffu, mA, 2));
        mB = fmaxf(mB, __shfl_xor_sync(0xffffffffu, mB, 1));
        mB = fmaxf(mB, __shfl_xor_sync(0xffffffffu, mB, 2));
        if ((lane & 3) == 0) {
            sMaxH[half * 64 + rA]     = mA;
            sMaxH[half * 64 + rA + 8] = mB;
        }
        __syncthreads();
        const float mxA = fmaxf(sMaxH[rA],     sMaxH[64 + rA]);
        const float mxB = fmaxf(sMaxH[rA + 8], sMaxH[64 + rA + 8]);

        float* outb = g_qp + ((size_t)bh * NN + n0) * MSTR;
        #pragma unroll
        for (int t = 0; t < 17; t++) {
            int m0 = colBase + t * 8 + (lane & 3) * 2;
            if (m0 < MM) {
                float2 vA = make_float2(RATIO * (__expf(acc[t][0] - dgA - mxA) + EPSV),
                                        RATIO * (__expf(acc[t][1] - dgA - mxA) + EPSV));
                float2 vB = make_float2(RATIO * (__expf(acc[t][2] - dgB - mxB) + EPSV),
                                        RATIO * (__expf(acc[t][3] - dgB - mxB) + EPSV));
                *(float2*)(outb + (size_t)rA * MSTR + m0)       = vA;
                *(float2*)(outb + (size_t)(rA + 8) * MSTR + m0) = vB;
            }
        }
    } else {
        float bm = NEGINF;
        float* outb = g_kd + ((size_t)bh * NN + n0) * MSTR;
        #pragma unroll
        for (int t = 0; t < 17; t++) {
            int m0 = colBase + t * 8 + (lane & 3) * 2;
            if (m0 < MM) {
                bm = fmaxf(bm, fmaxf(fmaxf(acc[t][0], acc[t][1]),
                                     fmaxf(acc[t][2], acc[t][3])));
                float2 vA = make_float2(acc[t][0] - dgA, acc[t][1] - dgA);
                float2 vB = make_float2(acc[t][2] - dgB, acc[t][3] - dgB);
                *(float2*)(outb + (size_t)rA * MSTR + m0)       = vA;
                *(float2*)(outb + (size_t)(rA + 8) * MSTR + m0) = vB;
            }
        }
        #pragma unroll
        for (int o = 16; o; o >>= 1) bm = fmaxf(bm, __shfl_xor_sync(0xffffffffu, bm, o));
        if (lane == 0) sRed[wid] = bm;
        __syncthreads();
        if (tid == 0) {
            float m2 = sRed[0];
            #pragma unroll
            for (int i = 1; i < 8; i++) m2 = fmaxf(m2, sRed[i]);
            unsigned u = __float_as_uint(m2);
            unsigned key = (u & 0x80000000u) ? ~u : (u | 0x80000000u);
            atomicMax(&g_kmax_bits, key);   // deterministic
        }
    }
}
#define SMEM_DASH ((64 * SXS + 272 * SPS + 64 + 128 + 8) * (int)sizeof(float))

// ===========================================================================
// ctx GEMM (rewritten): ctxT[e][m] = sum_n k'[n][m] v[n][e].
// hi/lo tf32 pairs pre-split into smem at staging; inner loop = LDS.64 + HMMA.
// Chunk = 32 n per stage; 3 CTAs/SM.
// ===========================================================================
#define PSTR 33   // uint2 pairs per row: 32 + 1 pad (row = 264B, 8B-aligned)

__global__ void __launch_bounds__(256, 3) k_ctx_mma(const float* __restrict__ V)
{
    __shared__ uint2 sA[64 * PSTR];    // [m-local][n-local] (hi,lo)
    __shared__ uint2 sB[ECT * PSTR];   // [e][n-local]; row 64 = ones

    const int tid = threadIdx.x, lane = tid & 31, wid = tid >> 5;
    const int m0 = blockIdx.x * 64;
    const int split = blockIdx.y, bh = blockIdx.z;
    const int n0 = split * (NN / SPLITC);

    unsigned key = g_kmax_bits;
    unsigned ub = (key & 0x80000000u) ? (key & 0x7FFFFFFFu) : ~key;
    const float stab = __uint_as_float(ub);

    const float* Kd = g_kd + (size_t)bh * NN * MSTR;
    const float* Vb = V + (size_t)bh * NN * EE;

    // static sB rows: ones(hi=1,lo=0) at e=64, zeros at 65..79
    for (int idx = tid; idx < 16 * PSTR; idx += 256) {
        int e = idx / PSTR;
        sB[(64 + e) * PSTR + (idx - e * PSTR)] =
            (e == 0) ? make_uint2(0x3F800000u, 0u) : make_uint2(0u, 0u);
    }

    const int rowGroup = wid >> 1, half = wid & 1;
    const int rA = rowGroup * 16 + (lane >> 2);
    const int colBase = half * 40;

    float acc[5][4];
    #pragma unroll
    for (int t = 0; t < 5; t++)
        #pragma unroll
        for (int j = 0; j < 4; j++) acc[t][j] = 0.f;

    const int nl = tid >> 3;              // n-local 0..31
    const int g8 = (tid & 7) * 8;         // 8-wide column group

    #pragma unroll 1
    for (int nc = 0; nc < NN / SPLITC; nc += 32) {
        __syncthreads();
        {   // stage A: k' (exp fused), hi/lo pre-split
            const float* src = Kd + (size_t)(n0 + nc + nl) * MSTR + m0 + g8;
            #pragma unroll
            for (int j = 0; j < 2; j++) {
                const int mb = m0 + g8 + j * 4;
                float4 x = (mb + 3 < MSTR) ? *(const float4*)(src + j * 4)
                                           : make_float4(0.f, 0.f, 0.f, 0.f);
                float xs[4] = {x.x, x.y, x.z, x.w};
                #pragma unroll
                for (int q = 0; q < 4; q++) {
                    float vv = (mb + q < MM) ? RATIO * (__expf(xs[q] - stab) + EPSV) : 0.f;
                    sA[(g8 + j * 4 + q) * PSTR + nl] = hilo(vv);
                }
            }
        }
        {   // stage B: v, hi/lo pre-split
            const float* src = Vb + (size_t)(n0 + nc + nl) * EE + g8;
            #pragma unroll
            for (int j = 0; j < 2; j++) {
                float4 x = *(const float4*)(src + j * 4);
                float xs[4] = {x.x, x.y, x.z, x.w};
                #pragma unroll
                for (int q = 0; q < 4; q++)
                    sB[(g8 + j * 4 + q) * PSTR + nl] = hilo(xs[q]);
            }
        }
        __syncthreads();

        #pragma unroll
        for (int k0 = 0; k0 < 32; k0 += 8) {
            const int c = k0 + (lane & 3);
            uint2 pa0 = sA[rA * PSTR + c];
            uint2 pa1 = sA[(rA + 8) * PSTR + c];
            uint2 pa2 = sA[rA * PSTR + c + 4];
            uint2 pa3 = sA[(rA + 8) * PSTR + c + 4];
            uint32_t aH[4] = {pa0.x, pa1.x, pa2.x, pa3.x};
            uint32_t aL[4] = {pa0.y, pa1.y, pa2.y, pa3.y};
            #pragma unroll
            for (int t = 0; t < 5; t++) {
                const int e = colBase + t * 8 + (lane >> 2);
                uint2 pb0 = sB[e * PSTR + c];
                uint2 pb1 = sB[e * PSTR + c + 4];
                uint32_t bH[2] = {pb0.x, pb1.x};
                uint32_t bL[2] = {pb0.y, pb1.y};
                mma8(acc[t], aH, bH);
                mma8(acc[t], aH, bL);
                mma8(acc[t], aL, bH);
            }
        }
    }

    float* dst = g_ctx_part + ((size_t)(split * BHc + bh)) * (ECT * MSTR);
    const int mA_ = m0 + rA, mB_ = m0 + rA + 8;
    #pragma unroll
    for (int t = 0; t < 5; t++) {
        int e0 = colBase + t * 8 + (lane & 3) * 2;
        if (mA_ < MSTR) {
            dst[(size_t)e0 * MSTR + mA_]       = acc[t][0];
            dst[(size_t)(e0 + 1) * MSTR + mA_] = acc[t][1];
        }
        if (mB_ < MSTR) {
            dst[(size_t)e0 * MSTR + mB_]       = acc[t][2];
            dst[(size_t)(e0 + 1) * MSTR + mB_] = acc[t][3];
        }
    }
}

__global__ void k_ctxT_reduce()
{
    size_t idx = (size_t)blockIdx.x * 256 + threadIdx.x;
    float s = 0.f;
    #pragma unroll
    for (int c = 0; c < SPLITC; c++)
        s += g_ctx_part[(size_t)c * (BHc * ECT * MSTR) + idx];
    g_ctxT[idx] = s;
}

// ===========================================================================
// out GEMM: out[n][e] = (q' @ ctxT^T)[n][e] / (q' @ kcum)[n], den = col 64.
// ===========================================================================
#define SOS 68

__global__ void __launch_bounds__(256, 3) k_out_mma(float* __restrict__ O)
{
    __shared__ float sA[64 * SOS];   // [n-local][k]
    __shared__ float sB[ECT * SOS];  // [e'][k]
    __shared__ float sDen[64];

    const int tid = threadIdx.x, lane = tid & 31, wid = tid >> 5;
    const int n0 = blockIdx.x * 64, bh = blockIdx.y;

    const float* Qp = g_qp + ((size_t)bh * NN + n0) * MSTR;
    const float* Ct = g_ctxT + (size_t)bh * ECT * MSTR;

    const int rowGroup = wid >> 1, half = wid & 1;
    const int rA = rowGroup * 16 + (lane >> 2);
    const int colBase = half * 40;

    float acc[5][4];
    #pragma unroll
    for (int t = 0; t < 5; t++)
        #pragma unroll
        for (int j = 0; j < 4; j++) acc[t][j] = 0.f;

    #pragma unroll 1
    for (int ch = 0; ch < 5; ch++) {
        const int k0g = ch * 64;
        const int kw = (ch == 4) ? 16 : 64;
        __syncthreads();
        {   // A: q' rows, direct
            const int row = tid >> 2, kq = (tid & 3) * 16;
            #pragma unroll
            for (int j = 0; j < 4; j++) {
                int k = kq + 4 * j;
                if (k < kw)
                    *(float4*)(sA + row * SOS + k) =
                        *(const float4*)(Qp + (size_t)row * MSTR + k0g + k);
            }
        }
        // B: ctxT rows, direct
        for (int idx = tid; idx < ECT * 16; idx += 256) {
            int e = idx >> 4, k4 = (idx & 15) * 4;
            if (k4 < kw)
                *(float4*)(sB + e * SOS + k4) =
                    *(const float4*)(Ct + (size_t)e * MSTR + k0g + k4);
        }
        __syncthreads();

        for (int k0 = 0; k0 < kw; k0 += 8) {
            uint32_t aH[4], aL[4];
            splitA(sA + (size_t)rA * SOS + k0 + (lane & 3), SOS, aH, aL);
            #pragma unroll
            for (int t = 0; t < 5; t++) {
                uint32_t bH[2], bL[2];
                splitB(sB + (size_t)(colBase + t * 8 + (lane >> 2)) * SOS + k0 + (lane & 3), bH, bL);
                mma8(acc[t], aH, bH);
                mma8(acc[t], aH, bL);
                mma8(acc[t], aL, bH);
            }
        }
    }

    // den: col 64 lives in half1, tile 3, (lane&3)==0
    if (half == 1 && (lane & 3) == 0) {
        sDen[rA]     = acc[3][0];
        sDen[rA + 8] = acc[3][2];
    }
    __syncthreads();
    const float dinvA = 1.f / sDen[rA];
    const float dinvB = 1.f / sDen[rA + 8];

    float* Ob = O + ((size_t)bh * NN + n0) * EE;
    #pragma unroll
    for (int t = 0; t < 5; t++) {
        int e0 = colBase + t * 8 + (lane & 3) * 2;
        if (e0 < EE) {
            *(float2*)(Ob + (size_t)rA * EE + e0) =
                make_float2(acc[t][0] * dinvA, acc[t][1] * dinvA);
            *(float2*)(Ob + (size_t)(rA + 8) * EE + e0) =
                make_float2(acc[t][2] * dinvB, acc[t][3] * dinvB);
        }
    }
}

// ---------------------------------------------------------------------------
extern "C" void kernel_launch(void* const* d_in, const int* in_sizes, int n_in,
                              void* d_out, int out_size)
{
    const float* q = (const float*)d_in[0];
    const float* k = (const float*)d_in[1];
    const float* v = (const float*)d_in[2];
    const float* P = (const float*)d_in[3];
    float* out = (float*)d_out;

    cudaFuncSetAttribute(k_dash_mma<true>,  cudaFuncAttributeMaxDynamicSharedMemorySize, SMEM_DASH);
    cudaFuncSetAttribute(k_dash_mma<false>, cudaFuncAttributeMaxDynamicSharedMemorySize, SMEM_DASH);

    k_reset<<<1, 32>>>();
    k_dash_mma<true><<<dim3(NN / 64, BHc), 256, SMEM_DASH>>>(q, P);
    k_dash_mma<false><<<dim3(NN / 64, BHc), 256, SMEM_DASH>>>(k, P);
    k_ctx_mma<<<dim3((MSTR + 63) / 64, SPLITC, BHc), 256>>>(v);
    k_ctxT_reduce<<<(BHc * ECT * MSTR) / 256, 256>>>();
    k_out_mma<<<dim3(NN / 64, BHc), 256>>>(out);
}

// round 9
// speedup vs baseline: 1.1814x; 1.1814x over previous
#include <cuda_runtime.h>
#include <cstdint>

// FastAttention (Performer / FAVOR+) — B=4 H=8 N=4096 D=64 M=266 E=64.
// Round 9: dash reverted to known-good R6 (in-loop tf32 split). ctx keeps the
// R8 presplit-pair layout (stride 36, conflict-free, in-bounds for 32 cols).
// out = R6 + (256,3) + carveout. R8 bug was dash rows (64 pairs) overrunning
// the 36-pair stride.

#define BHc 32
#define NN  4096
#define DD  64
#define MM  266
#define MSTR 272
#define EE  64
#define ECT 80

#define DN     0.3535533905932738f
#define RATIO  0.06131393394849658f
#define EPSV   1e-4f
#define NEGINF (-3.402823466e38f)

#define SPLITC 2

// ---- scratch ----
__device__ float    g_qp[BHc * NN * MSTR];       // q' (pads [266,272) stay 0)
__device__ float    g_kd[BHc * NN * MSTR];       // dash - diag (pads stay 0)
__device__ unsigned g_kmax_bits;
__device__ float    g_ctx_part[SPLITC * BHc * ECT * MSTR];
__device__ float    g_ctxT[BHc * ECT * MSTR];    // [bh][e][m]; row 64 = kcum

__global__ void k_reset() { if (threadIdx.x == 0) g_kmax_bits = 0u; }

// =====================  helpers  ======================

__device__ __forceinline__ uint32_t f2tf32(float x) {
    uint32_t r; asm("cvt.rna.tf32.f32 %0, %1;" : "=r"(r) : "f"(x)); return r;
}
__device__ __forceinline__ uint2 hilo(float x) {
    uint32_t h = f2tf32(x);
    uint32_t l = f2tf32(x - __uint_as_float(h));
    return make_uint2(h, l);
}
__device__ __forceinline__ void mma8(float* d, const uint32_t* a, const uint32_t* b) {
    asm volatile(
        "mma.sync.aligned.m16n8k8.row.col.f32.tf32.tf32.f32 "
        "{%0,%1,%2,%3}, {%4,%5,%6,%7}, {%8,%9}, {%0,%1,%2,%3};"
        : "+f"(d[0]), "+f"(d[1]), "+f"(d[2]), "+f"(d[3])
        : "r"(a[0]), "r"(a[1]), "r"(a[2]), "r"(a[3]), "r"(b[0]), "r"(b[1]));
}
__device__ __forceinline__ void splitA(const float* ax, int strd, uint32_t* aH, uint32_t* aL) {
    float a0 = ax[0], a1 = ax[8 * strd], a2 = ax[4], a3 = ax[8 * strd + 4];
    aH[0] = f2tf32(a0); aL[0] = f2tf32(a0 - __uint_as_float(aH[0]));
    aH[1] = f2tf32(a1); aL[1] = f2tf32(a1 - __uint_as_float(aH[1]));
    aH[2] = f2tf32(a2); aL[2] = f2tf32(a2 - __uint_as_float(aH[2]));
    aH[3] = f2tf32(a3); aL[3] = f2tf32(a3 - __uint_as_float(aH[3]));
}
__device__ __forceinline__ void splitB(const float* bx, uint32_t* bH, uint32_t* bL) {
    float b0 = bx[0], b1 = bx[4];
    bH[0] = f2tf32(b0); bL[0] = f2tf32(b0 - __uint_as_float(bH[0]));
    bH[1] = f2tf32(b1); bL[1] = f2tf32(b1 - __uint_as_float(bH[1]));
}
__device__ __forceinline__ void mma3(float* d, const uint2* a, const uint2* b) {
    uint32_t aH[4] = {a[0].x, a[1].x, a[2].x, a[3].x};
    uint32_t aL[4] = {a[0].y, a[1].y, a[2].y, a[3].y};
    uint32_t bH[2] = {b[0].x, b[1].x};
    uint32_t bL[2] = {b[0].y, b[1].y};
    mma8(d, aH, bH);
    mma8(d, aH, bL);
    mma8(d, aL, bH);
}

// ===========================================================================
// dash GEMM (R6 verbatim): CTA = 64 n x 272 m x K=64, in-loop tf32 split.
// ===========================================================================
#define SXS 68
#define SPS 68

template <bool IS_Q>
__global__ void __launch_bounds__(256, 2) k_dash_mma(const float* __restrict__ X,
                                                     const float* __restrict__ P)
{
    extern __shared__ float sh[];
    float* sX    = sh;                    // [64][68]
    float* sP    = sh + 64 * SXS;         // [272][68]
    float* sDiag = sP + 272 * SPS;        // [64]
    float* sMaxH = sDiag + 64;            // [2][64]
    float* sRed  = sMaxH + 128;           // [8]

    const int tid = threadIdx.x, lane = tid & 31, wid = tid >> 5;
    const int bh = blockIdx.y, n0 = blockIdx.x * 64;

    {   // X tile (scaled) + per-row diag
        const int row = tid >> 2, kq = (tid & 3) * 16;
        const float* src = X + ((size_t)bh * NN + n0 + row) * DD + kq;
        float ss = 0.f;
        #pragma unroll
        for (int j = 0; j < 4; j++) {
            float4 v = *(const float4*)(src + j * 4);
            float x0 = v.x * DN, x1 = v.y * DN, x2 = v.z * DN, x3 = v.w * DN;
            float* d = sX + row * SXS + kq + j * 4;
            d[0] = x0; d[1] = x1; d[2] = x2; d[3] = x3;
            ss = fmaf(x0, x0, ss); ss = fmaf(x1, x1, ss);
            ss = fmaf(x2, x2, ss); ss = fmaf(x3, x3, ss);
        }
        ss += __shfl_xor_sync(0xffffffffu, ss, 1);
        ss += __shfl_xor_sync(0xffffffffu, ss, 2);
        if ((tid & 3) == 0) sDiag[row] = 0.5f * ss;
    }
    for (int t = tid; t < 272 * 4; t += 256) {   // P (zero-padded past 266)
        const int row = t >> 2, kq = (t & 3) * 16;
        const bool valid = row < MM;
        const float* src = P + (size_t)row * DD + kq;
        float* d = sP + row * SPS + kq;
        #pragma unroll
        for (int j = 0; j < 4; j++) {
            float4 v = valid ? *(const float4*)(src + j * 4)
                             : make_float4(0.f, 0.f, 0.f, 0.f);
            d[j * 4 + 0] = v.x; d[j * 4 + 1] = v.y;
            d[j * 4 + 2] = v.z; d[j * 4 + 3] = v.w;
        }
    }
    __syncthreads();

    const int rowGroup = wid >> 1, half = wid & 1;
    const int rA = rowGroup * 16 + (lane >> 2);
    const int colBase = half * 136;

    float acc[17][4];
    #pragma unroll
    for (int t = 0; t < 17; t++)
        #pragma unroll
        for (int j = 0; j < 4; j++) acc[t][j] = 0.f;

    #pragma unroll 1
    for (int k0 = 0; k0 < 64; k0 += 8) {
        uint32_t aH[4], aL[4];
        splitA(sX + (size_t)rA * SXS + k0 + (lane & 3), SXS, aH, aL);
        #pragma unroll
        for (int t = 0; t < 17; t++) {
            uint32_t bH[2], bL[2];
            splitB(sP + (size_t)(colBase + t * 8 + (lane >> 2)) * SPS + k0 + (lane & 3), bH, bL);
            mma8(acc[t], aH, bH);
            mma8(acc[t], aH, bL);
            mma8(acc[t], aL, bH);
        }
    }

    const float dgA = sDiag[rA], dgB = sDiag[rA + 8];

    if (IS_Q) {
        float mA = NEGINF, mB = NEGINF;
        #pragma unroll
        for (int t = 0; t < 17; t++) {
            int m0 = colBase + t * 8 + (lane & 3) * 2;
            if (m0 < MM) {
                mA = fmaxf(mA, fmaxf(acc[t][0], acc[t][1]));
                mB = fmaxf(mB, fmaxf(acc[t][2], acc[t][3]));
            }
        }
        mA = fmaxf(mA, __shfl_xor_sync(0xffffffffu, mA, 1));
        mA = fmaxf(mA, __shfl_xor_sync(0xffffffffu, mA, 2));
        mB = fmaxf(mB, __shfl_xor_sync(0xffffffffu, mB, 1));
        mB = fmaxf(mB, __shfl_xor_sync(0xffffffffu, mB, 2));
        if ((lane & 3) == 0) {
            sMaxH[half * 64 + rA]     = mA;
            sMaxH[half * 64 + rA + 8] = mB;
        }
        __syncthreads();
        const float mxA = fmaxf(sMaxH[rA],     sMaxH[64 + rA]);
        const float mxB = fmaxf(sMaxH[rA + 8], sMaxH[64 + rA + 8]);

        float* outb = g_qp + ((size_t)bh * NN + n0) * MSTR;
        #pragma unroll
        for (int t = 0; t < 17; t++) {
            int m0 = colBase + t * 8 + (lane & 3) * 2;
            if (m0 < MM) {
                float2 vA = make_float2(RATIO * (__expf(acc[t][0] - dgA - mxA) + EPSV),
                                        RATIO * (__expf(acc[t][1] - dgA - mxA) + EPSV));
                float2 vB = make_float2(RATIO * (__expf(acc[t][2] - dgB - mxB) + EPSV),
                                        RATIO * (__expf(acc[t][3] - dgB - mxB) + EPSV));
                *(float2*)(outb + (size_t)rA * MSTR + m0)       = vA;
                *(float2*)(outb + (size_t)(rA + 8) * MSTR + m0) = vB;
            }
        }
    } else {
        float bm = NEGINF;
        float* outb = g_kd + ((size_t)bh * NN + n0) * MSTR;
        #pragma unroll
        for (int t = 0; t < 17; t++) {
            int m0 = colBase + t * 8 + (lane & 3) * 2;
            if (m0 < MM) {
                bm = fmaxf(bm, fmaxf(fmaxf(acc[t][0], acc[t][1]),
                                     fmaxf(acc[t][2], acc[t][3])));
                float2 vA = make_float2(acc[t][0] - dgA, acc[t][1] - dgA);
                float2 vB = make_float2(acc[t][2] - dgB, acc[t][3] - dgB);
                *(float2*)(outb + (size_t)rA * MSTR + m0)       = vA;
                *(float2*)(outb + (size_t)(rA + 8) * MSTR + m0) = vB;
            }
        }
        #pragma unroll
        for (int o = 16; o; o >>= 1) bm = fmaxf(bm, __shfl_xor_sync(0xffffffffu, bm, o));
        if (lane == 0) sRed[wid] = bm;
        __syncthreads();
        if (tid == 0) {
            float m2 = sRed[0];
            #pragma unroll
            for (int i = 1; i < 8; i++) m2 = fmaxf(m2, sRed[i]);
            unsigned u = __float_as_uint(m2);
            unsigned key = (u & 0x80000000u) ? ~u : (u | 0x80000000u);
            atomicMax(&g_kmax_bits, key);
        }
    }
}
#define SMEM_DASH ((64 * SXS + 272 * SPS + 64 + 128 + 8) * (int)sizeof(float))

// ===========================================================================
// ctx GEMM (R8, correct): presplit (hi,lo) pairs, stride 36 (conflict-free,
// 32 n-cols per chunk fit), exp fused in staging; kcum = ones-column at e=64.
// ===========================================================================
#define PSTR 36

__global__ void __launch_bounds__(256, 3) k_ctx_mma(const float* __restrict__ V)
{
    __shared__ uint2 sA[64 * PSTR];    // [m-local][n-local]
    __shared__ uint2 sB[ECT * PSTR];   // [e][n-local]; row 64 = ones

    const int tid = threadIdx.x, lane = tid & 31, wid = tid >> 5;
    const int m0 = blockIdx.x * 64;
    const int split = blockIdx.y, bh = blockIdx.z;
    const int n0 = split * (NN / SPLITC);

    unsigned key = g_kmax_bits;
    unsigned ub = (key & 0x80000000u) ? (key & 0x7FFFFFFFu) : ~key;
    const float stab = __uint_as_float(ub);

    const float* Kd = g_kd + (size_t)bh * NN * MSTR;
    const float* Vb = V + (size_t)bh * NN * EE;

    for (int idx = tid; idx < 16 * PSTR; idx += 256) {
        int e = idx / PSTR;
        sB[(64 + e) * PSTR + (idx - e * PSTR)] =
            (e == 0) ? make_uint2(0x3F800000u, 0u) : make_uint2(0u, 0u);
    }

    const int rowGroup = wid >> 1, half = wid & 1;
    const int rA = rowGroup * 16 + (lane >> 2);
    const int colBase = half * 40;
    const int cb = lane & 3, qr = lane >> 2;

    float acc[5][4];
    #pragma unroll
    for (int t = 0; t < 5; t++)
        #pragma unroll
        for (int j = 0; j < 4; j++) acc[t][j] = 0.f;

    const int nl = tid >> 3;              // n-local 0..31
    const int g8 = (tid & 7) * 8;         // 8-wide column group

    #pragma unroll 1
    for (int nc = 0; nc < NN / SPLITC; nc += 32) {
        __syncthreads();
        {   // stage A: k' (exp fused), presplit pairs
            const float* src = Kd + (size_t)(n0 + nc + nl) * MSTR + m0 + g8;
            #pragma unroll
            for (int j = 0; j < 2; j++) {
                const int mb = m0 + g8 + j * 4;
                float4 x = (mb + 3 < MSTR) ? *(const float4*)(src + j * 4)
                                           : make_float4(0.f, 0.f, 0.f, 0.f);
                float xs[4] = {x.x, x.y, x.z, x.w};
                #pragma unroll
                for (int q = 0; q < 4; q++) {
                    float vv = (mb + q < MM) ? RATIO * (__expf(xs[q] - stab) + EPSV) : 0.f;
                    sA[(g8 + j * 4 + q) * PSTR + nl] = hilo(vv);
                }
            }
        }
        {   // stage B: v, presplit pairs
            const float* src = Vb + (size_t)(n0 + nc + nl) * EE + g8;
            #pragma unroll
            for (int j = 0; j < 2; j++) {
                float4 x = *(const float4*)(src + j * 4);
                float xs[4] = {x.x, x.y, x.z, x.w};
                #pragma unroll
                for (int q = 0; q < 4; q++)
                    sB[(g8 + j * 4 + q) * PSTR + nl] = hilo(xs[q]);
            }
        }
        __syncthreads();

        #pragma unroll
        for (int k0 = 0; k0 < 32; k0 += 8) {
            const int c = k0 + cb;
            uint2 a[4];
            a[0] = sA[rA * PSTR + c];
            a[1] = sA[(rA + 8) * PSTR + c];
            a[2] = sA[rA * PSTR + c + 4];
            a[3] = sA[(rA + 8) * PSTR + c + 4];
            #pragma unroll
            for (int t = 0; t < 5; t++) {
                const int e = colBase + t * 8 + qr;
                uint2 b[2] = {sB[e * PSTR + c], sB[e * PSTR + c + 4]};
                mma3(acc[t], a, b);
            }
        }
    }

    float* dst = g_ctx_part + ((size_t)(split * BHc + bh)) * (ECT * MSTR);
    const int mA_ = m0 + rA, mB_ = m0 + rA + 8;
    #pragma unroll
    for (int t = 0; t < 5; t++) {
        int e0 = colBase + t * 8 + cb * 2;
        if (mA_ < MSTR) {
            dst[(size_t)e0 * MSTR + mA_]       = acc[t][0];
            dst[(size_t)(e0 + 1) * MSTR + mA_] = acc[t][1];
        }
        if (mB_ < MSTR) {
            dst[(size_t)e0 * MSTR + mB_]       = acc[t][2];
            dst[(size_t)(e0 + 1) * MSTR + mB_] = acc[t][3];
        }
    }
}

__global__ void k_ctxT_reduce()
{
    size_t idx = (size_t)blockIdx.x * 256 + threadIdx.x;
    float s = 0.f;
    #pragma unroll
    for (int c = 0; c < SPLITC; c++)
        s += g_ctx_part[(size_t)c * (BHc * ECT * MSTR) + idx];
    g_ctxT[idx] = s;
}

// ===========================================================================
// out GEMM: out[n][e] = (q' @ ctxT^T)[n][e] / den, den = col 64.
// ===========================================================================
#define SOS 68

__global__ void __launch_bounds__(256, 3) k_out_mma(float* __restrict__ O)
{
    __shared__ float sA[64 * SOS];
    __shared__ float sB[ECT * SOS];
    __shared__ float sDen[64];

    const int tid = threadIdx.x, lane = tid & 31, wid = tid >> 5;
    const int n0 = blockIdx.x * 64, bh = blockIdx.y;

    const float* Qp = g_qp + ((size_t)bh * NN + n0) * MSTR;
    const float* Ct = g_ctxT + (size_t)bh * ECT * MSTR;

    const int rowGroup = wid >> 1, half = wid & 1;
    const int rA = rowGroup * 16 + (lane >> 2);
    const int colBase = half * 40;

    float acc[5][4];
    #pragma unroll
    for (int t = 0; t < 5; t++)
        #pragma unroll
        for (int j = 0; j < 4; j++) acc[t][j] = 0.f;

    #pragma unroll 1
    for (int ch = 0; ch < 5; ch++) {
        const int k0g = ch * 64;
        const int kw = (ch == 4) ? 16 : 64;
        __syncthreads();
        {
            const int row = tid >> 2, kq = (tid & 3) * 16;
            #pragma unroll
            for (int j = 0; j < 4; j++) {
                int k = kq + 4 * j;
                if (k < kw)
                    *(float4*)(sA + row * SOS + k) =
                        *(const float4*)(Qp + (size_t)row * MSTR + k0g + k);
            }
        }
        for (int idx = tid; idx < ECT * 16; idx += 256) {
            int e = idx >> 4, k4 = (idx & 15) * 4;
            if (k4 < kw)
                *(float4*)(sB + e * SOS + k4) =
                    *(const float4*)(Ct + (size_t)e * MSTR + k0g + k4);
        }
        __syncthreads();

        for (int k0 = 0; k0 < kw; k0 += 8) {
            uint32_t aH[4], aL[4];
            splitA(sA + (size_t)rA * SOS + k0 + (lane & 3), SOS, aH, aL);
            #pragma unroll
            for (int t = 0; t < 5; t++) {
                uint32_t bH[2], bL[2];
                splitB(sB + (size_t)(colBase + t * 8 + (lane >> 2)) * SOS + k0 + (lane & 3), bH, bL);
                mma8(acc[t], aH, bH);
                mma8(acc[t], aH, bL);
                mma8(acc[t], aL, bH);
            }
        }
    }

    if (half == 1 && (lane & 3) == 0) {
        sDen[rA]     = acc[3][0];
        sDen[rA + 8] = acc[3][2];
    }
    __syncthreads();
    const float dinvA = 1.f / sDen[rA];
    const float dinvB = 1.f / sDen[rA + 8];

    float* Ob = O + ((size_t)bh * NN + n0) * EE;
    #pragma unroll
    for (int t = 0; t < 5; t++) {
        int e0 = colBase + t * 8 + (lane & 3) * 2;
        if (e0 < EE) {
            *(float2*)(Ob + (size_t)rA * EE + e0) =
                make_float2(acc[t][0] * dinvA, acc[t][1] * dinvA);
            *(float2*)(Ob + (size_t)(rA + 8) * EE + e0) =
                make_float2(acc[t][2] * dinvB, acc[t][3] * dinvB);
        }
    }
}

// ---------------------------------------------------------------------------
extern "C" void kernel_launch(void* const* d_in, const int* in_sizes, int n_in,
                              void* d_out, int out_size)
{
    const float* q = (const float*)d_in[0];
    const float* k = (const float*)d_in[1];
    const float* v = (const float*)d_in[2];
    const float* P = (const float*)d_in[3];
    float* out = (float*)d_out;

    cudaFuncSetAttribute(k_dash_mma<true>,  cudaFuncAttributeMaxDynamicSharedMemorySize, SMEM_DASH);
    cudaFuncSetAttribute(k_dash_mma<false>, cudaFuncAttributeMaxDynamicSharedMemorySize, SMEM_DASH);
    cudaFuncSetAttribute(k_dash_mma<true>,  cudaFuncAttributePreferredSharedMemoryCarveout, 100);
    cudaFuncSetAttribute(k_dash_mma<false>, cudaFuncAttributePreferredSharedMemoryCarveout, 100);
    cudaFuncSetAttribute(k_ctx_mma,         cudaFuncAttributePreferredSharedMemoryCarveout, 100);
    cudaFuncSetAttribute(k_out_mma,         cudaFuncAttributePreferredSharedMemoryCarveout, 100);

    k_reset<<<1, 32>>>();
    k_dash_mma<true><<<dim3(NN / 64, BHc), 256, SMEM_DASH>>>(q, P);
    k_dash_mma<false><<<dim3(NN / 64, BHc), 256, SMEM_DASH>>>(k, P);
    k_ctx_mma<<<dim3((MSTR + 63) / 64, SPLITC, BHc), 256>>>(v);
    k_ctxT_reduce<<<(BHc * ECT * MSTR) / 256, 256>>>();
    k_out_mma<<<dim3(NN / 64, BHc), 256>>>(out);
}

// round 10
// speedup vs baseline: 1.3798x; 1.1679x over previous
#include <cuda_runtime.h>
#include <cstdint>

// FastAttention (Performer / FAVOR+) — B=4 H=8 N=4096 D=64 M=266 E=64.
// Round 10: ctx staging stores made conflict-free by keeping gmem order
// ([n][m]/[n][e] pair rows) and transposing on the fragment LOAD instead
// (stride 68/84 pairs => 2-way max). Dash = R6 verbatim; out = R9.

#define BHc 32
#define NN  4096
#define DD  64
#define MM  266
#define MSTR 272
#define EE  64
#define ECT 80

#define DN     0.3535533905932738f
#define RATIO  0.06131393394849658f
#define EPSV   1e-4f
#define NEGINF (-3.402823466e38f)

#define SPLITC 2

// ---- scratch ----
__device__ float    g_qp[BHc * NN * MSTR];       // q' (pads [266,272) stay 0)
__device__ float    g_kd[BHc * NN * MSTR];       // dash - diag (pads stay 0)
__device__ unsigned g_kmax_bits;
__device__ float    g_ctx_part[SPLITC * BHc * ECT * MSTR];
__device__ float    g_ctxT[BHc * ECT * MSTR];    // [bh][e][m]; row 64 = kcum

__global__ void k_reset() { if (threadIdx.x == 0) g_kmax_bits = 0u; }

// =====================  helpers  ======================

__device__ __forceinline__ uint32_t f2tf32(float x) {
    uint32_t r; asm("cvt.rna.tf32.f32 %0, %1;" : "=r"(r) : "f"(x)); return r;
}
__device__ __forceinline__ uint2 hilo(float x) {
    uint32_t h = f2tf32(x);
    uint32_t l = f2tf32(x - __uint_as_float(h));
    return make_uint2(h, l);
}
__device__ __forceinline__ void mma8(float* d, const uint32_t* a, const uint32_t* b) {
    asm volatile(
        "mma.sync.aligned.m16n8k8.row.col.f32.tf32.tf32.f32 "
        "{%0,%1,%2,%3}, {%4,%5,%6,%7}, {%8,%9}, {%0,%1,%2,%3};"
        : "+f"(d[0]), "+f"(d[1]), "+f"(d[2]), "+f"(d[3])
        : "r"(a[0]), "r"(a[1]), "r"(a[2]), "r"(a[3]), "r"(b[0]), "r"(b[1]));
}
__device__ __forceinline__ void splitA(const float* ax, int strd, uint32_t* aH, uint32_t* aL) {
    float a0 = ax[0], a1 = ax[8 * strd], a2 = ax[4], a3 = ax[8 * strd + 4];
    aH[0] = f2tf32(a0); aL[0] = f2tf32(a0 - __uint_as_float(aH[0]));
    aH[1] = f2tf32(a1); aL[1] = f2tf32(a1 - __uint_as_float(aH[1]));
    aH[2] = f2tf32(a2); aL[2] = f2tf32(a2 - __uint_as_float(aH[2]));
    aH[3] = f2tf32(a3); aL[3] = f2tf32(a3 - __uint_as_float(aH[3]));
}
__device__ __forceinline__ void splitB(const float* bx, uint32_t* bH, uint32_t* bL) {
    float b0 = bx[0], b1 = bx[4];
    bH[0] = f2tf32(b0); bL[0] = f2tf32(b0 - __uint_as_float(bH[0]));
    bH[1] = f2tf32(b1); bL[1] = f2tf32(b1 - __uint_as_float(bH[1]));
}
__device__ __forceinline__ void mma3(float* d, const uint2* a, const uint2* b) {
    uint32_t aH[4] = {a[0].x, a[1].x, a[2].x, a[3].x};
    uint32_t aL[4] = {a[0].y, a[1].y, a[2].y, a[3].y};
    uint32_t bH[2] = {b[0].x, b[1].x};
    uint32_t bL[2] = {b[0].y, b[1].y};
    mma8(d, aH, bH);
    mma8(d, aH, bL);
    mma8(d, aL, bH);
}

// ===========================================================================
// dash GEMM (R6 verbatim): CTA = 64 n x 272 m x K=64, in-loop tf32 split.
// ===========================================================================
#define SXS 68
#define SPS 68

template <bool IS_Q>
__global__ void __launch_bounds__(256, 2) k_dash_mma(const float* __restrict__ X,
                                                     const float* __restrict__ P)
{
    extern __shared__ float sh[];
    float* sX    = sh;                    // [64][68]
    float* sP    = sh + 64 * SXS;         // [272][68]
    float* sDiag = sP + 272 * SPS;        // [64]
    float* sMaxH = sDiag + 64;            // [2][64]
    float* sRed  = sMaxH + 128;           // [8]

    const int tid = threadIdx.x, lane = tid & 31, wid = tid >> 5;
    const int bh = blockIdx.y, n0 = blockIdx.x * 64;

    {   // X tile (scaled) + per-row diag
        const int row = tid >> 2, kq = (tid & 3) * 16;
        const float* src = X + ((size_t)bh * NN + n0 + row) * DD + kq;
        float ss = 0.f;
        #pragma unroll
        for (int j = 0; j < 4; j++) {
            float4 v = *(const float4*)(src + j * 4);
            float x0 = v.x * DN, x1 = v.y * DN, x2 = v.z * DN, x3 = v.w * DN;
            float* d = sX + row * SXS + kq + j * 4;
            d[0] = x0; d[1] = x1; d[2] = x2; d[3] = x3;
            ss = fmaf(x0, x0, ss); ss = fmaf(x1, x1, ss);
            ss = fmaf(x2, x2, ss); ss = fmaf(x3, x3, ss);
        }
        ss += __shfl_xor_sync(0xffffffffu, ss, 1);
        ss += __shfl_xor_sync(0xffffffffu, ss, 2);
        if ((tid & 3) == 0) sDiag[row] = 0.5f * ss;
    }
    for (int t = tid; t < 272 * 4; t += 256) {   // P (zero-padded past 266)
        const int row = t >> 2, kq = (t & 3) * 16;
        const bool valid = row < MM;
        const float* src = P + (size_t)row * DD + kq;
        float* d = sP + row * SPS + kq;
        #pragma unroll
        for (int j = 0; j < 4; j++) {
            float4 v = valid ? *(const float4*)(src + j * 4)
                             : make_float4(0.f, 0.f, 0.f, 0.f);
            d[j * 4 + 0] = v.x; d[j * 4 + 1] = v.y;
            d[j * 4 + 2] = v.z; d[j * 4 + 3] = v.w;
        }
    }
    __syncthreads();

    const int rowGroup = wid >> 1, half = wid & 1;
    const int rA = rowGroup * 16 + (lane >> 2);
    const int colBase = half * 136;

    float acc[17][4];
    #pragma unroll
    for (int t = 0; t < 17; t++)
        #pragma unroll
        for (int j = 0; j < 4; j++) acc[t][j] = 0.f;

    #pragma unroll 1
    for (int k0 = 0; k0 < 64; k0 += 8) {
        uint32_t aH[4], aL[4];
        splitA(sX + (size_t)rA * SXS + k0 + (lane & 3), SXS, aH, aL);
        #pragma unroll
        for (int t = 0; t < 17; t++) {
            uint32_t bH[2], bL[2];
            splitB(sP + (size_t)(colBase + t * 8 + (lane >> 2)) * SPS + k0 + (lane & 3), bH, bL);
            mma8(acc[t], aH, bH);
            mma8(acc[t], aH, bL);
            mma8(acc[t], aL, bH);
        }
    }

    const float dgA = sDiag[rA], dgB = sDiag[rA + 8];

    if (IS_Q) {
        float mA = NEGINF, mB = NEGINF;
        #pragma unroll
        for (int t = 0; t < 17; t++) {
            int m0 = colBase + t * 8 + (lane & 3) * 2;
            if (m0 < MM) {
                mA = fmaxf(mA, fmaxf(acc[t][0], acc[t][1]));
                mB = fmaxf(mB, fmaxf(acc[t][2], acc[t][3]));
            }
        }
        mA = fmaxf(mA, __shfl_xor_sync(0xffffffffu, mA, 1));
        mA = fmaxf(mA, __shfl_xor_sync(0xffffffffu, mA, 2));
        mB = fmaxf(mB, __shfl_xor_sync(0xffffffffu, mB, 1));
        mB = fmaxf(mB, __shfl_xor_sync(0xffffffffu, mB, 2));
        if ((lane & 3) == 0) {
            sMaxH[half * 64 + rA]     = mA;
            sMaxH[half * 64 + rA + 8] = mB;
        }
        __syncthreads();
        const float mxA = fmaxf(sMaxH[rA],     sMaxH[64 + rA]);
        const float mxB = fmaxf(sMaxH[rA + 8], sMaxH[64 + rA + 8]);

        float* outb = g_qp + ((size_t)bh * NN + n0) * MSTR;
        #pragma unroll
        for (int t = 0; t < 17; t++) {
            int m0 = colBase + t * 8 + (lane & 3) * 2;
            if (m0 < MM) {
                float2 vA = make_float2(RATIO * (__expf(acc[t][0] - dgA - mxA) + EPSV),
                                        RATIO * (__expf(acc[t][1] - dgA - mxA) + EPSV));
                float2 vB = make_float2(RATIO * (__expf(acc[t][2] - dgB - mxB) + EPSV),
                                        RATIO * (__expf(acc[t][3] - dgB - mxB) + EPSV));
                *(float2*)(outb + (size_t)rA * MSTR + m0)       = vA;
                *(float2*)(outb + (size_t)(rA + 8) * MSTR + m0) = vB;
            }
        }
    } else {
        float bm = NEGINF;
        float* outb = g_kd + ((size_t)bh * NN + n0) * MSTR;
        #pragma unroll
        for (int t = 0; t < 17; t++) {
            int m0 = colBase + t * 8 + (lane & 3) * 2;
            if (m0 < MM) {
                bm = fmaxf(bm, fmaxf(fmaxf(acc[t][0], acc[t][1]),
                                     fmaxf(acc[t][2], acc[t][3])));
                float2 vA = make_float2(acc[t][0] - dgA, acc[t][1] - dgA);
                float2 vB = make_float2(acc[t][2] - dgB, acc[t][3] - dgB);
                *(float2*)(outb + (size_t)rA * MSTR + m0)       = vA;
                *(float2*)(outb + (size_t)(rA + 8) * MSTR + m0) = vB;
            }
        }
        #pragma unroll
        for (int o = 16; o; o >>= 1) bm = fmaxf(bm, __shfl_xor_sync(0xffffffffu, bm, o));
        if (lane == 0) sRed[wid] = bm;
        __syncthreads();
        if (tid == 0) {
            float m2 = sRed[0];
            #pragma unroll
            for (int i = 1; i < 8; i++) m2 = fmaxf(m2, sRed[i]);
            unsigned u = __float_as_uint(m2);
            unsigned key = (u & 0x80000000u) ? ~u : (u | 0x80000000u);
            atomicMax(&g_kmax_bits, key);
        }
    }
}
#define SMEM_DASH ((64 * SXS + 272 * SPS + 64 + 128 + 8) * (int)sizeof(float))

// ===========================================================================
// ctx GEMM: ctxT[e][m] = sum_n k'[n][m] v[n][e]; exp fused in staging.
// smem keeps gmem order ([n][m], [n][e'] pair rows) -> conflict-free stores;
// fragments transpose on load (stride 68/84 pairs => <=2-way).
// kcum = ones-column at e'=64 (rows 64..79 of each n initialized once).
// ===========================================================================
#define SAP 68    // pairs per sA row: 64 m + 4 pad (68 mod 16 == 4)
#define SBP 84    // pairs per sB row: 80 e' + 4 pad (84 mod 16 == 4)

__global__ void __launch_bounds__(256, 3) k_ctx_mma(const float* __restrict__ V)
{
    __shared__ uint2 sA[32 * SAP];   // [n-local][m-local] pairs
    __shared__ uint2 sB[32 * SBP];   // [n-local][e'] pairs; e'=64 ones

    const int tid = threadIdx.x, lane = tid & 31, wid = tid >> 5;
    const int m0 = blockIdx.x * 64;
    const int split = blockIdx.y, bh = blockIdx.z;
    const int n0 = split * (NN / SPLITC);

    unsigned key = g_kmax_bits;
    unsigned ub = (key & 0x80000000u) ? (key & 0x7FFFFFFFu) : ~key;
    const float stab = __uint_as_float(ub);

    const float* Kd = g_kd + (size_t)bh * NN * MSTR;
    const float* Vb = V + (size_t)bh * NN * EE;

    // ones/zero columns e' = 64..79 of every n-row (written once)
    for (int idx = tid; idx < 32 * 16; idx += 256) {
        int n = idx >> 4, e = 64 + (idx & 15);
        sB[n * SBP + e] = (e == 64) ? make_uint2(0x3F800000u, 0u)
                                    : make_uint2(0u, 0u);
    }

    const int rowGroup = wid >> 1, half = wid & 1;
    const int rA = rowGroup * 16 + (lane >> 2);
    const int colBase = half * 40;
    const int cb = lane & 3, qr = lane >> 2;

    float acc[5][4];
    #pragma unroll
    for (int t = 0; t < 5; t++)
        #pragma unroll
        for (int j = 0; j < 4; j++) acc[t][j] = 0.f;

    const int nl = tid >> 3;              // n-local 0..31
    const int mseg = (tid & 7) * 8;       // 8-wide segment

    #pragma unroll 1
    for (int nc = 0; nc < NN / SPLITC; nc += 32) {
        __syncthreads();
        {   // stage A: k' (exp fused), pairs in row order -> conflict-free STS
            const float* src = Kd + (size_t)(n0 + nc + nl) * MSTR + m0 + mseg;
            #pragma unroll
            for (int j = 0; j < 2; j++) {
                const int mb = m0 + mseg + j * 4;
                float4 x = (mb + 3 < MSTR) ? *(const float4*)(src + j * 4)
                                           : make_float4(0.f, 0.f, 0.f, 0.f);
                float xs[4] = {x.x, x.y, x.z, x.w};
                uint2 p[4];
                #pragma unroll
                for (int q = 0; q < 4; q++) {
                    float vv = (mb + q < MM) ? RATIO * (__expf(xs[q] - stab) + EPSV) : 0.f;
                    p[q] = hilo(vv);
                }
                uint2* dstp = sA + nl * SAP + mseg + j * 4;
                *(uint4*)(dstp)     = make_uint4(p[0].x, p[0].y, p[1].x, p[1].y);
                *(uint4*)(dstp + 2) = make_uint4(p[2].x, p[2].y, p[3].x, p[3].y);
            }
        }
        {   // stage B: v pairs, row order
            const float* src = Vb + (size_t)(n0 + nc + nl) * EE + mseg;
            #pragma unroll
            for (int j = 0; j < 2; j++) {
                float4 x = *(const float4*)(src + j * 4);
                float xs[4] = {x.x, x.y, x.z, x.w};
                uint2 p[4];
                #pragma unroll
                for (int q = 0; q < 4; q++) p[q] = hilo(xs[q]);
                uint2* dstp = sB + nl * SBP + mseg + j * 4;
                *(uint4*)(dstp)     = make_uint4(p[0].x, p[0].y, p[1].x, p[1].y);
                *(uint4*)(dstp + 2) = make_uint4(p[2].x, p[2].y, p[3].x, p[3].y);
            }
        }
        __syncthreads();

        #pragma unroll
        for (int k0 = 0; k0 < 32; k0 += 8) {
            const int c = k0 + cb;          // k (= n-local) index
            uint2 a[4];
            a[0] = sA[c * SAP + rA];        // A[m=rA][k=c]
            a[1] = sA[c * SAP + rA + 8];
            a[2] = sA[(c + 4) * SAP + rA];
            a[3] = sA[(c + 4) * SAP + rA + 8];
            #pragma unroll
            for (int t = 0; t < 5; t++) {
                const int e = colBase + t * 8 + qr;
                uint2 b[2] = {sB[c * SBP + e], sB[(c + 4) * SBP + e]};
                mma3(acc[t], a, b);
            }
        }
    }

    float* dst = g_ctx_part + ((size_t)(split * BHc + bh)) * (ECT * MSTR);
    const int mA_ = m0 + rA, mB_ = m0 + rA + 8;
    #pragma unroll
    for (int t = 0; t < 5; t++) {
        int e0 = colBase + t * 8 + cb * 2;
        if (mA_ < MSTR) {
            dst[(size_t)e0 * MSTR + mA_]       = acc[t][0];
            dst[(size_t)(e0 + 1) * MSTR + mA_] = acc[t][1];
        }
        if (mB_ < MSTR) {
            dst[(size_t)e0 * MSTR + mB_]       = acc[t][2];
            dst[(size_t)(e0 + 1) * MSTR + mB_] = acc[t][3];
        }
    }
}

__global__ void k_ctxT_reduce()
{
    size_t idx = (size_t)blockIdx.x * 256 + threadIdx.x;
    float s = 0.f;
    #pragma unroll
    for (int c = 0; c < SPLITC; c++)
        s += g_ctx_part[(size_t)c * (BHc * ECT * MSTR) + idx];
    g_ctxT[idx] = s;
}

// ===========================================================================
// out GEMM: out[n][e] = (q' @ ctxT^T)[n][e] / den, den = col 64.
// ===========================================================================
#define SOS 68

__global__ void __launch_bounds__(256, 3) k_out_mma(float* __restrict__ O)
{
    __shared__ float sA[64 * SOS];
    __shared__ float sB[ECT * SOS];
    __shared__ float sDen[64];

    const int tid = threadIdx.x, lane = tid & 31, wid = tid >> 5;
    const int n0 = blockIdx.x * 64, bh = blockIdx.y;

    const float* Qp = g_qp + ((size_t)bh * NN + n0) * MSTR;
    const float* Ct = g_ctxT + (size_t)bh * ECT * MSTR;

    const int rowGroup = wid >> 1, half = wid & 1;
    const int rA = rowGroup * 16 + (lane >> 2);
    const int colBase = half * 40;

    float acc[5][4];
    #pragma unroll
    for (int t = 0; t < 5; t++)
        #pragma unroll
        for (int j = 0; j < 4; j++) acc[t][j] = 0.f;

    #pragma unroll 1
    for (int ch = 0; ch < 5; ch++) {
        const int k0g = ch * 64;
        const int kw = (ch == 4) ? 16 : 64;
        __syncthreads();
        {
            const int row = tid >> 2, kq = (tid & 3) * 16;
            #pragma unroll
            for (int j = 0; j < 4; j++) {
                int k = kq + 4 * j;
                if (k < kw)
                    *(float4*)(sA + row * SOS + k) =
                        *(const float4*)(Qp + (size_t)row * MSTR + k0g + k);
            }
        }
        for (int idx = tid; idx < ECT * 16; idx += 256) {
            int e = idx >> 4, k4 = (idx & 15) * 4;
            if (k4 < kw)
                *(float4*)(sB + e * SOS + k4) =
                    *(const float4*)(Ct + (size_t)e * MSTR + k0g + k4);
        }
        __syncthreads();

        for (int k0 = 0; k0 < kw; k0 += 8) {
            uint32_t aH[4], aL[4];
            splitA(sA + (size_t)rA * SOS + k0 + (lane & 3), SOS, aH, aL);
            #pragma unroll
            for (int t = 0; t < 5; t++) {
                uint32_t bH[2], bL[2];
                splitB(sB + (size_t)(colBase + t * 8 + (lane >> 2)) * SOS + k0 + (lane & 3), bH, bL);
                mma8(acc[t], aH, bH);
                mma8(acc[t], aH, bL);
                mma8(acc[t], aL, bH);
            }
        }
    }

    if (half == 1 && (lane & 3) == 0) {
        sDen[rA]     = acc[3][0];
        sDen[rA + 8] = acc[3][2];
    }
    __syncthreads();
    const float dinvA = 1.f / sDen[rA];
    const float dinvB = 1.f / sDen[rA + 8];

    float* Ob = O + ((size_t)bh * NN + n0) * EE;
    #pragma unroll
    for (int t = 0; t < 5; t++) {
        int e0 = colBase + t * 8 + (lane & 3) * 2;
        if (e0 < EE) {
            *(float2*)(Ob + (size_t)rA * EE + e0) =
                make_float2(acc[t][0] * dinvA, acc[t][1] * dinvA);
            *(float2*)(Ob + (size_t)(rA + 8) * EE + e0) =
                make_float2(acc[t][2] * dinvB, acc[t][3] * dinvB);
        }
    }
}

// ---------------------------------------------------------------------------
extern "C" void kernel_launch(void* const* d_in, const int* in_sizes, int n_in,
                              void* d_out, int out_size)
{
    const float* q = (const float*)d_in[0];
    const float* k = (const float*)d_in[1];
    const float* v = (const float*)d_in[2];
    const float* P = (const float*)d_in[3];
    float* out = (float*)d_out;

    cudaFuncSetAttribute(k_dash_mma<true>,  cudaFuncAttributeMaxDynamicSharedMemorySize, SMEM_DASH);
    cudaFuncSetAttribute(k_dash_mma<false>, cudaFuncAttributeMaxDynamicSharedMemorySize, SMEM_DASH);
    cudaFuncSetAttribute(k_dash_mma<true>,  cudaFuncAttributePreferredSharedMemoryCarveout, 100);
    cudaFuncSetAttribute(k_dash_mma<false>, cudaFuncAttributePreferredSharedMemoryCarveout, 100);
    cudaFuncSetAttribute(k_ctx_mma,         cudaFuncAttributePreferredSharedMemoryCarveout, 100);
    cudaFuncSetAttribute(k_out_mma,         cudaFuncAttributePreferredSharedMemoryCarveout, 100);

    k_reset<<<1, 32>>>();
    k_dash_mma<true><<<dim3(NN / 64, BHc), 256, SMEM_DASH>>>(q, P);
    k_dash_mma<false><<<dim3(NN / 64, BHc), 256, SMEM_DASH>>>(k, P);
    k_ctx_mma<<<dim3((MSTR + 63) / 64, SPLITC, BHc), 256>>>(v);
    k_ctxT_reduce<<<(BHc * ECT * MSTR) / 256, 256>>>();
    k_out_mma<<<dim3(NN / 64, BHc), 256>>>(out);
}

// round 11
// speedup vs baseline: 1.5254x; 1.1055x over previous
#include <cuda_runtime.h>
#include <cstdint>

// FastAttention (Performer / FAVOR+) — B=4 H=8 N=4096 D=64 M=266 E=64.
// Round 11: ctx occupancy fix — SPLITC 8 (grid 320 -> 1280 CTAs; occupancy
// was grid-limited at 2.16/SM). e-pad trimmed 80 -> 72 (asymmetric warp
// tiles 5/4), saving ~10% MMA in ctx and out. Dash = R6 verbatim.

#define BHc 32
#define NN  4096
#define DD  64
#define MM  266
#define MSTR 272
#define EE  64
#define ECT 80            // gmem ctx rows (72..79 stay zero, never consumed)

#define DN     0.3535533905932738f
#define RATIO  0.06131393394849658f
#define EPSV   1e-4f
#define NEGINF (-3.402823466e38f)

#define SPLITC 8

// ---- scratch ----
__device__ float    g_qp[BHc * NN * MSTR];       // q' (pads [266,272) stay 0)
__device__ float    g_kd[BHc * NN * MSTR];       // dash - diag (pads stay 0)
__device__ unsigned g_kmax_bits;
__device__ float    g_ctx_part[SPLITC * BHc * ECT * MSTR];
__device__ float    g_ctxT[BHc * ECT * MSTR];    // [bh][e][m]; row 64 = kcum

__global__ void k_reset() { if (threadIdx.x == 0) g_kmax_bits = 0u; }

// =====================  helpers  ======================

__device__ __forceinline__ uint32_t f2tf32(float x) {
    uint32_t r; asm("cvt.rna.tf32.f32 %0, %1;" : "=r"(r) : "f"(x)); return r;
}
__device__ __forceinline__ uint2 hilo(float x) {
    uint32_t h = f2tf32(x);
    uint32_t l = f2tf32(x - __uint_as_float(h));
    return make_uint2(h, l);
}
__device__ __forceinline__ void mma8(float* d, const uint32_t* a, const uint32_t* b) {
    asm volatile(
        "mma.sync.aligned.m16n8k8.row.col.f32.tf32.tf32.f32 "
        "{%0,%1,%2,%3}, {%4,%5,%6,%7}, {%8,%9}, {%0,%1,%2,%3};"
        : "+f"(d[0]), "+f"(d[1]), "+f"(d[2]), "+f"(d[3])
        : "r"(a[0]), "r"(a[1]), "r"(a[2]), "r"(a[3]), "r"(b[0]), "r"(b[1]));
}
__device__ __forceinline__ void splitA(const float* ax, int strd, uint32_t* aH, uint32_t* aL) {
    float a0 = ax[0], a1 = ax[8 * strd], a2 = ax[4], a3 = ax[8 * strd + 4];
    aH[0] = f2tf32(a0); aL[0] = f2tf32(a0 - __uint_as_float(aH[0]));
    aH[1] = f2tf32(a1); aL[1] = f2tf32(a1 - __uint_as_float(aH[1]));
    aH[2] = f2tf32(a2); aL[2] = f2tf32(a2 - __uint_as_float(aH[2]));
    aH[3] = f2tf32(a3); aL[3] = f2tf32(a3 - __uint_as_float(aH[3]));
}
__device__ __forceinline__ void splitB(const float* bx, uint32_t* bH, uint32_t* bL) {
    float b0 = bx[0], b1 = bx[4];
    bH[0] = f2tf32(b0); bL[0] = f2tf32(b0 - __uint_as_float(bH[0]));
    bH[1] = f2tf32(b1); bL[1] = f2tf32(b1 - __uint_as_float(bH[1]));
}
__device__ __forceinline__ void mma3(float* d, const uint2* a, const uint2* b) {
    uint32_t aH[4] = {a[0].x, a[1].x, a[2].x, a[3].x};
    uint32_t aL[4] = {a[0].y, a[1].y, a[2].y, a[3].y};
    uint32_t bH[2] = {b[0].x, b[1].x};
    uint32_t bL[2] = {b[0].y, b[1].y};
    mma8(d, aH, bH);
    mma8(d, aH, bL);
    mma8(d, aL, bH);
}

// ===========================================================================
// dash GEMM (R6 verbatim): CTA = 64 n x 272 m x K=64, in-loop tf32 split.
// ===========================================================================
#define SXS 68
#define SPS 68

template <bool IS_Q>
__global__ void __launch_bounds__(256, 2) k_dash_mma(const float* __restrict__ X,
                                                     const float* __restrict__ P)
{
    extern __shared__ float sh[];
    float* sX    = sh;                    // [64][68]
    float* sP    = sh + 64 * SXS;         // [272][68]
    float* sDiag = sP + 272 * SPS;        // [64]
    float* sMaxH = sDiag + 64;            // [2][64]
    float* sRed  = sMaxH + 128;           // [8]

    const int tid = threadIdx.x, lane = tid & 31, wid = tid >> 5;
    const int bh = blockIdx.y, n0 = blockIdx.x * 64;

    {   // X tile (scaled) + per-row diag
        const int row = tid >> 2, kq = (tid & 3) * 16;
        const float* src = X + ((size_t)bh * NN + n0 + row) * DD + kq;
        float ss = 0.f;
        #pragma unroll
        for (int j = 0; j < 4; j++) {
            float4 v = *(const float4*)(src + j * 4);
            float x0 = v.x * DN, x1 = v.y * DN, x2 = v.z * DN, x3 = v.w * DN;
            float* d = sX + row * SXS + kq + j * 4;
            d[0] = x0; d[1] = x1; d[2] = x2; d[3] = x3;
            ss = fmaf(x0, x0, ss); ss = fmaf(x1, x1, ss);
            ss = fmaf(x2, x2, ss); ss = fmaf(x3, x3, ss);
        }
        ss += __shfl_xor_sync(0xffffffffu, ss, 1);
        ss += __shfl_xor_sync(0xffffffffu, ss, 2);
        if ((tid & 3) == 0) sDiag[row] = 0.5f * ss;
    }
    for (int t = tid; t < 272 * 4; t += 256) {   // P (zero-padded past 266)
        const int row = t >> 2, kq = (t & 3) * 16;
        const bool valid = row < MM;
        const float* src = P + (size_t)row * DD + kq;
        float* d = sP + row * SPS + kq;
        #pragma unroll
        for (int j = 0; j < 4; j++) {
            float4 v = valid ? *(const float4*)(src + j * 4)
                             : make_float4(0.f, 0.f, 0.f, 0.f);
            d[j * 4 + 0] = v.x; d[j * 4 + 1] = v.y;
            d[j * 4 + 2] = v.z; d[j * 4 + 3] = v.w;
        }
    }
    __syncthreads();

    const int rowGroup = wid >> 1, half = wid & 1;
    const int rA = rowGroup * 16 + (lane >> 2);
    const int colBase = half * 136;

    float acc[17][4];
    #pragma unroll
    for (int t = 0; t < 17; t++)
        #pragma unroll
        for (int j = 0; j < 4; j++) acc[t][j] = 0.f;

    #pragma unroll 1
    for (int k0 = 0; k0 < 64; k0 += 8) {
        uint32_t aH[4], aL[4];
        splitA(sX + (size_t)rA * SXS + k0 + (lane & 3), SXS, aH, aL);
        #pragma unroll
        for (int t = 0; t < 17; t++) {
            uint32_t bH[2], bL[2];
            splitB(sP + (size_t)(colBase + t * 8 + (lane >> 2)) * SPS + k0 + (lane & 3), bH, bL);
            mma8(acc[t], aH, bH);
            mma8(acc[t], aH, bL);
            mma8(acc[t], aL, bH);
        }
    }

    const float dgA = sDiag[rA], dgB = sDiag[rA + 8];

    if (IS_Q) {
        float mA = NEGINF, mB = NEGINF;
        #pragma unroll
        for (int t = 0; t < 17; t++) {
            int m0 = colBase + t * 8 + (lane & 3) * 2;
            if (m0 < MM) {
                mA = fmaxf(mA, fmaxf(acc[t][0], acc[t][1]));
                mB = fmaxf(mB, fmaxf(acc[t][2], acc[t][3]));
            }
        }
        mA = fmaxf(mA, __shfl_xor_sync(0xffffffffu, mA, 1));
        mA = fmaxf(mA, __shfl_xor_sync(0xffffffffu, mA, 2));
        mB = fmaxf(mB, __shfl_xor_sync(0xffffffffu, mB, 1));
        mB = fmaxf(mB, __shfl_xor_sync(0xffffffffu, mB, 2));
        if ((lane & 3) == 0) {
            sMaxH[half * 64 + rA]     = mA;
            sMaxH[half * 64 + rA + 8] = mB;
        }
        __syncthreads();
        const float mxA = fmaxf(sMaxH[rA],     sMaxH[64 + rA]);
        const float mxB = fmaxf(sMaxH[rA + 8], sMaxH[64 + rA + 8]);

        float* outb = g_qp + ((size_t)bh * NN + n0) * MSTR;
        #pragma unroll
        for (int t = 0; t < 17; t++) {
            int m0 = colBase + t * 8 + (lane & 3) * 2;
            if (m0 < MM) {
                float2 vA = make_float2(RATIO * (__expf(acc[t][0] - dgA - mxA) + EPSV),
                                        RATIO * (__expf(acc[t][1] - dgA - mxA) + EPSV));
                float2 vB = make_float2(RATIO * (__expf(acc[t][2] - dgB - mxB) + EPSV),
                                        RATIO * (__expf(acc[t][3] - dgB - mxB) + EPSV));
                *(float2*)(outb + (size_t)rA * MSTR + m0)       = vA;
                *(float2*)(outb + (size_t)(rA + 8) * MSTR + m0) = vB;
            }
        }
    } else {
        float bm = NEGINF;
        float* outb = g_kd + ((size_t)bh * NN + n0) * MSTR;
        #pragma unroll
        for (int t = 0; t < 17; t++) {
            int m0 = colBase + t * 8 + (lane & 3) * 2;
            if (m0 < MM) {
                bm = fmaxf(bm, fmaxf(fmaxf(acc[t][0], acc[t][1]),
                                     fmaxf(acc[t][2], acc[t][3])));
                float2 vA = make_float2(acc[t][0] - dgA, acc[t][1] - dgA);
                float2 vB = make_float2(acc[t][2] - dgB, acc[t][3] - dgB);
                *(float2*)(outb + (size_t)rA * MSTR + m0)       = vA;
                *(float2*)(outb + (size_t)(rA + 8) * MSTR + m0) = vB;
            }
        }
        #pragma unroll
        for (int o = 16; o; o >>= 1) bm = fmaxf(bm, __shfl_xor_sync(0xffffffffu, bm, o));
        if (lane == 0) sRed[wid] = bm;
        __syncthreads();
        if (tid == 0) {
            float m2 = sRed[0];
            #pragma unroll
            for (int i = 1; i < 8; i++) m2 = fmaxf(m2, sRed[i]);
            unsigned u = __float_as_uint(m2);
            unsigned key = (u & 0x80000000u) ? ~u : (u | 0x80000000u);
            atomicMax(&g_kmax_bits, key);
        }
    }
}
#define SMEM_DASH ((64 * SXS + 272 * SPS + 64 + 128 + 8) * (int)sizeof(float))

// ===========================================================================
// ctx GEMM: ctxT[e][m] = sum_n k'[n][m] v[n][e]; exp fused in staging.
// smem in gmem order (conflict-free STS), fragments transpose on load.
// e-cols 0..71: half0 warps own e 0..39 (5 tiles), half1 own 40..71 (4).
// kcum = ones-column at e=64. Split-K = 8 for occupancy (grid 1280).
// ===========================================================================
#define SAP 68    // pairs per sA row (68 mod 16 == 4)
#define SBP 76    // pairs per sB row: 72 e' + 4 pad (76 mod 16 == 12, 2-way max)

__global__ void __launch_bounds__(256, 3) k_ctx_mma(const float* __restrict__ V)
{
    __shared__ uint2 sA[32 * SAP];   // [n-local][m-local] pairs
    __shared__ uint2 sB[32 * SBP];   // [n-local][e'] pairs; e'=64 ones

    const int tid = threadIdx.x, lane = tid & 31, wid = tid >> 5;
    const int m0 = blockIdx.x * 64;
    const int split = blockIdx.y, bh = blockIdx.z;
    const int n0 = split * (NN / SPLITC);

    unsigned key = g_kmax_bits;
    unsigned ub = (key & 0x80000000u) ? (key & 0x7FFFFFFFu) : ~key;
    const float stab = __uint_as_float(ub);

    const float* Kd = g_kd + (size_t)bh * NN * MSTR;
    const float* Vb = V + (size_t)bh * NN * EE;

    // ones/zero columns e' = 64..71 of every n-row (written once)
    for (int idx = tid; idx < 32 * 8; idx += 256) {
        int n = idx >> 3, e = 64 + (idx & 7);
        sB[n * SBP + e] = (e == 64) ? make_uint2(0x3F800000u, 0u)
                                    : make_uint2(0u, 0u);
    }

    const int rowGroup = wid >> 1, half = wid & 1;
    const int rA = rowGroup * 16 + (lane >> 2);
    const int colBase = half * 40;
    const int NT = half ? 4 : 5;          // tiles: e 0..39 | 40..71
    const int cb = lane & 3, qr = lane >> 2;

    float acc[5][4];
    #pragma unroll
    for (int t = 0; t < 5; t++)
        #pragma unroll
        for (int j = 0; j < 4; j++) acc[t][j] = 0.f;

    const int nl = tid >> 3;              // n-local 0..31
    const int mseg = (tid & 7) * 8;       // 8-wide segment

    #pragma unroll 1
    for (int nc = 0; nc < NN / SPLITC; nc += 32) {
        __syncthreads();
        {   // stage A: k' (exp fused), pairs in row order -> conflict-free STS
            const float* src = Kd + (size_t)(n0 + nc + nl) * MSTR + m0 + mseg;
            #pragma unroll
            for (int j = 0; j < 2; j++) {
                const int mb = m0 + mseg + j * 4;
                float4 x = (mb + 3 < MSTR) ? *(const float4*)(src + j * 4)
                                           : make_float4(0.f, 0.f, 0.f, 0.f);
                float xs[4] = {x.x, x.y, x.z, x.w};
                uint2 p[4];
                #pragma unroll
                for (int q = 0; q < 4; q++) {
                    float vv = (mb + q < MM) ? RATIO * (__expf(xs[q] - stab) + EPSV) : 0.f;
                    p[q] = hilo(vv);
                }
                uint2* dstp = sA + nl * SAP + mseg + j * 4;
                *(uint4*)(dstp)     = make_uint4(p[0].x, p[0].y, p[1].x, p[1].y);
                *(uint4*)(dstp + 2) = make_uint4(p[2].x, p[2].y, p[3].x, p[3].y);
            }
        }
        {   // stage B: v pairs, row order
            const float* src = Vb + (size_t)(n0 + nc + nl) * EE + mseg;
            #pragma unroll
            for (int j = 0; j < 2; j++) {
                float4 x = *(const float4*)(src + j * 4);
                float xs[4] = {x.x, x.y, x.z, x.w};
                uint2 p[4];
                #pragma unroll
                for (int q = 0; q < 4; q++) p[q] = hilo(xs[q]);
                uint2* dstp = sB + nl * SBP + mseg + j * 4;
                *(uint4*)(dstp)     = make_uint4(p[0].x, p[0].y, p[1].x, p[1].y);
                *(uint4*)(dstp + 2) = make_uint4(p[2].x, p[2].y, p[3].x, p[3].y);
            }
        }
        __syncthreads();

        #pragma unroll
        for (int k0 = 0; k0 < 32; k0 += 8) {
            const int c = k0 + cb;          // k (= n-local) index
            uint2 a[4];
            a[0] = sA[c * SAP + rA];        // A[m=rA][k=c]
            a[1] = sA[c * SAP + rA + 8];
            a[2] = sA[(c + 4) * SAP + rA];
            a[3] = sA[(c + 4) * SAP + rA + 8];
            #pragma unroll
            for (int t = 0; t < 5; t++) {
                if (t < NT) {
                    const int e = colBase + t * 8 + qr;
                    uint2 b[2] = {sB[c * SBP + e], sB[(c + 4) * SBP + e]};
                    mma3(acc[t], a, b);
                }
            }
        }
    }

    float* dst = g_ctx_part + ((size_t)(split * BHc + bh)) * (ECT * MSTR);
    const int mA_ = m0 + rA, mB_ = m0 + rA + 8;
    #pragma unroll
    for (int t = 0; t < 5; t++) {
        if (t < NT) {
            int e0 = colBase + t * 8 + cb * 2;
            if (mA_ < MSTR) {
                dst[(size_t)e0 * MSTR + mA_]       = acc[t][0];
                dst[(size_t)(e0 + 1) * MSTR + mA_] = acc[t][1];
            }
            if (mB_ < MSTR) {
                dst[(size_t)e0 * MSTR + mB_]       = acc[t][2];
                dst[(size_t)(e0 + 1) * MSTR + mB_] = acc[t][3];
            }
        }
    }
}

__global__ void k_ctxT_reduce()
{
    size_t idx = (size_t)blockIdx.x * 256 + threadIdx.x;
    float s = 0.f;
    #pragma unroll
    for (int c = 0; c < SPLITC; c++)
        s += g_ctx_part[(size_t)c * (BHc * ECT * MSTR) + idx];
    g_ctxT[idx] = s;
}

// ===========================================================================
// out GEMM: out[n][e] = (q' @ ctxT^T)[n][e] / den, den = col 64.
// Asymmetric tiles: half0 e 0..39 (5 tiles), half1 e 40..71 (4 tiles).
// ===========================================================================
#define SOS 68

__global__ void __launch_bounds__(256, 3) k_out_mma(float* __restrict__ O)
{
    __shared__ float sA[64 * SOS];
    __shared__ float sB[72 * SOS];
    __shared__ float sDen[64];

    const int tid = threadIdx.x, lane = tid & 31, wid = tid >> 5;
    const int n0 = blockIdx.x * 64, bh = blockIdx.y;

    const float* Qp = g_qp + ((size_t)bh * NN + n0) * MSTR;
    const float* Ct = g_ctxT + (size_t)bh * ECT * MSTR;

    const int rowGroup = wid >> 1, half = wid & 1;
    const int rA = rowGroup * 16 + (lane >> 2);
    const int colBase = half * 40;
    const int NT = half ? 4 : 5;

    float acc[5][4];
    #pragma unroll
    for (int t = 0; t < 5; t++)
        #pragma unroll
        for (int j = 0; j < 4; j++) acc[t][j] = 0.f;

    #pragma unroll 1
    for (int ch = 0; ch < 5; ch++) {
        const int k0g = ch * 64;
        const int kw = (ch == 4) ? 16 : 64;
        __syncthreads();
        {
            const int row = tid >> 2, kq = (tid & 3) * 16;
            #pragma unroll
            for (int j = 0; j < 4; j++) {
                int k = kq + 4 * j;
                if (k < kw)
                    *(float4*)(sA + row * SOS + k) =
                        *(const float4*)(Qp + (size_t)row * MSTR + k0g + k);
            }
        }
        for (int idx = tid; idx < 72 * 16; idx += 256) {
            int e = idx >> 4, k4 = (idx & 15) * 4;
            if (k4 < kw)
                *(float4*)(sB + e * SOS + k4) =
                    *(const float4*)(Ct + (size_t)e * MSTR + k0g + k4);
        }
        __syncthreads();

        for (int k0 = 0; k0 < kw; k0 += 8) {
            uint32_t aH[4], aL[4];
            splitA(sA + (size_t)rA * SOS + k0 + (lane & 3), SOS, aH, aL);
            #pragma unroll
            for (int t = 0; t < 5; t++) {
                if (t < NT) {
                    uint32_t bH[2], bL[2];
                    splitB(sB + (size_t)(colBase + t * 8 + (lane >> 2)) * SOS + k0 + (lane & 3), bH, bL);
                    mma8(acc[t], aH, bH);
                    mma8(acc[t], aH, bL);
                    mma8(acc[t], aL, bH);
                }
            }
        }
    }

    if (half == 1 && (lane & 3) == 0) {
        sDen[rA]     = acc[3][0];
        sDen[rA + 8] = acc[3][2];
    }
    __syncthreads();
    const float dinvA = 1.f / sDen[rA];
    const float dinvB = 1.f / sDen[rA + 8];

    float* Ob = O + ((size_t)bh * NN + n0) * EE;
    #pragma unroll
    for (int t = 0; t < 5; t++) {
        int e0 = colBase + t * 8 + (lane & 3) * 2;
        if (t < NT && e0 < EE) {
            *(float2*)(Ob + (size_t)rA * EE + e0) =
                make_float2(acc[t][0] * dinvA, acc[t][1] * dinvA);
            *(float2*)(Ob + (size_t)(rA + 8) * EE + e0) =
                make_float2(acc[t][2] * dinvB, acc[t][3] * dinvB);
        }
    }
}

// ---------------------------------------------------------------------------
extern "C" void kernel_launch(void* const* d_in, const int* in_sizes, int n_in,
                              void* d_out, int out_size)
{
    const float* q = (const float*)d_in[0];
    const float* k = (const float*)d_in[1];
    const float* v = (const float*)d_in[2];
    const float* P = (const float*)d_in[3];
    float* out = (float*)d_out;

    cudaFuncSetAttribute(k_dash_mma<true>,  cudaFuncAttributeMaxDynamicSharedMemorySize, SMEM_DASH);
    cudaFuncSetAttribute(k_dash_mma<false>, cudaFuncAttributeMaxDynamicSharedMemorySize, SMEM_DASH);
    cudaFuncSetAttribute(k_dash_mma<true>,  cudaFuncAttributePreferredSharedMemoryCarveout, 100);
    cudaFuncSetAttribute(k_dash_mma<false>, cudaFuncAttributePreferredSharedMemoryCarveout, 100);
    cudaFuncSetAttribute(k_ctx_mma,         cudaFuncAttributePreferredSharedMemoryCarveout, 100);
    cudaFuncSetAttribute(k_out_mma,         cudaFuncAttributePreferredSharedMemoryCarveout, 100);

    k_reset<<<1, 32>>>();
    k_dash_mma<true><<<dim3(NN / 64, BHc), 256, SMEM_DASH>>>(q, P);
    k_dash_mma<false><<<dim3(NN / 64, BHc), 256, SMEM_DASH>>>(k, P);
    k_ctx_mma<<<dim3((MSTR + 63) / 64, SPLITC, BHc), 256>>>(v);
    k_ctxT_reduce<<<(BHc * ECT * MSTR) / 256, 256>>>();
    k_out_mma<<<dim3(NN / 64, BHc), 256>>>(out);
}